// round 11
// baseline (speedup 1.0000x reference)
#include <cuda_runtime.h>
#include <cuda_fp16.h>
#include <cstdint>

#define NPTS 1000000
#define WRES 64

// Transposed grids in fp16, layout [3, H, W, 16] per scale, concatenated.
// per-scale half counts: s0 393216, s1 786432, s2 1572864, s3 3145728
__device__ __align__(16) __half g_trans[5898240];

// -------- fused transpose+convert: [3,16,H,64] fp32 -> [3,H,64,16] fp16 --------
__global__ void __launch_bounds__(256) transpose_all(const float* __restrict__ g0,
                                                     const float* __restrict__ g1,
                                                     const float* __restrict__ g2,
                                                     const float* __restrict__ g3) {
    int idx = blockIdx.x * blockDim.x + threadIdx.x;
    if (idx >= 368640) return;   // 3*64*(128+256+512+1024)
    const float* g;
    int H, toff, local, hshift;
    if (idx < 24576)       { g = g0; H = 128;  toff = 0;       local = idx;          hshift = 7;  }
    else if (idx < 73728)  { g = g1; H = 256;  toff = 393216;  local = idx - 24576;  hshift = 8;  }
    else if (idx < 172032) { g = g2; H = 512;  toff = 1179648; local = idx - 73728;  hshift = 9;  }
    else                   { g = g3; H = 1024; toff = 2752512; local = idx - 172032; hshift = 10; }

    int w = local & 63;
    int rest = local >> 6;            // ci*H + h
    int h = rest & (H - 1);
    int ci = rest >> hshift;
    const float* src = g + ((size_t)(ci * 16) * H + h) * WRES + w;
    float tmp[16];
    size_t fstride = (size_t)H * WRES;
#pragma unroll
    for (int f = 0; f < 16; f++) tmp[f] = src[f * fstride];

    __half2 hv[8];
#pragma unroll
    for (int f = 0; f < 8; f++) hv[f] = __floats2half2_rn(tmp[2 * f], tmp[2 * f + 1]);

    uint4* dst = reinterpret_cast<uint4*>(g_trans + toff + (size_t)local * 16);
    uint4 a, b;
    a.x = *(uint32_t*)&hv[0]; a.y = *(uint32_t*)&hv[1];
    a.z = *(uint32_t*)&hv[2]; a.w = *(uint32_t*)&hv[3];
    b.x = *(uint32_t*)&hv[4]; b.y = *(uint32_t*)&hv[5];
    b.z = *(uint32_t*)&hv[6]; b.w = *(uint32_t*)&hv[7];
    dst[0] = a;
    dst[1] = b;
}

// -------- main sample kernel: 4 lanes x 4 samples (all scales) per thread --------
// Group G = n*3 + ci handles j = ci, ci+3, ci+6, ci+9 (scales 0..3), which share
// the x coordinate (pts[n,ci]) and the y source (radius[n]).
// lane r: bit0 = feature half (16B chunk), bit1 = x-corner.
__global__ void __launch_bounds__(256) sample_k(const float* __restrict__ pts,
                                                const float* __restrict__ radius,
                                                float* __restrict__ out) {
    int t = blockIdx.x * blockDim.x + threadIdx.x;
    int G = t >> 2;               // 3M groups
    int r = t & 3;
    int n = G / 3;
    int ci = G - n * 3;           // 0..2

    float xv = __ldg(pts + n * 3 + ci);
    float yv = __ldg(radius + n);

    // shared x setup
    float fx = (xv + 1.0f) * 31.5f;
    float x0f = floorf(fx);
    float wx = fx - x0f;
    int x0 = min(max((int)x0f, 0), 63);
    int x1 = min(x0 + 1, 63);
    int xs = (r & 2) ? x1 : x0;
    int hsel = (r & 1) * 8;
    float wxr = (r & 2) ? wx : (1.0f - wx);
    float yp1 = yv + 1.0f;

    // per-scale y setup + address computation (8 independent loads, MLP=8)
    uint4 v0[4], v1[4];           // v0[s] = row y0 of scale s, v1[s] = row y1
    float w0[4], w1[4];
#pragma unroll
    for (int s = 0; s < 4; s++) {
        int H = 128 << s;
        float fy = yp1 * (0.5f * (float)(H - 1));
        float y0f = floorf(fy);
        float wy = fy - y0f;
        int y0 = min(max((int)y0f, 0), H - 1);
        int y1i = min(y0 + 1, H - 1);
        int toff = 393216 * ((1 << s) - 1);
        const __half* tb = g_trans + toff + (size_t)(ci * H) * (WRES * 16);
        v0[s] = *reinterpret_cast<const uint4*>(tb + (size_t)((y0 << 6) + xs) * 16 + hsel);
        v1[s] = *reinterpret_cast<const uint4*>(tb + (size_t)((y1i << 6) + xs) * 16 + hsel);
        w0[s] = (1.0f - wy) * wxr;
        w1[s] = wy * wxr;
    }

    // out base for this (n, ci, chunk): sample s lands at obase + s*48
    int chunk = ((r & 1) << 1) | (r >> 1);
    float* obase = out + (size_t)n * 192 + ci * 16 + chunk * 4;

#pragma unroll
    for (int s = 0; s < 4; s++) {
        const __half2* hA = reinterpret_cast<const __half2*>(&v0[s]);
        const __half2* hB = reinterpret_cast<const __half2*>(&v1[s]);
        float acc[8];
#pragma unroll
        for (int k = 0; k < 4; k++) {
            float2 a = __half22float2(hA[k]);
            float2 b = __half22float2(hB[k]);
            acc[2 * k]     = a.x * w0[s] + b.x * w1[s];
            acc[2 * k + 1] = a.y * w0[s] + b.y * w1[s];
        }
#pragma unroll
        for (int i = 0; i < 8; i++) acc[i] += __shfl_xor_sync(0xffffffffu, acc[i], 2);

        float4 st = (r & 2) ? make_float4(acc[4], acc[5], acc[6], acc[7])
                            : make_float4(acc[0], acc[1], acc[2], acc[3]);
        *reinterpret_cast<float4*>(obase + s * 48) = st;
    }
}

extern "C" void kernel_launch(void* const* d_in, const int* in_sizes, int n_in,
                              void* d_out, int out_size) {
    const float* pts    = (const float*)d_in[0];
    const float* radius = (const float*)d_in[1];
    float* out = (float*)d_out;

    transpose_all<<<(368640 + 255) / 256, 256>>>((const float*)d_in[2],
                                                 (const float*)d_in[3],
                                                 (const float*)d_in[4],
                                                 (const float*)d_in[5]);

    // 3M groups * 4 lanes = 12M threads; 256/block -> 46875 blocks exactly
    sample_k<<<46875, 256>>>(pts, radius, out);
}

// round 12
// speedup vs baseline: 1.0649x; 1.0649x over previous
#include <cuda_runtime.h>
#include <cuda_fp16.h>
#include <cstdint>

#define NPTS 1000000
#define WRES 64

// Duplicated-pair grid in fp16: per (scale, ci, y, x) a 64B-aligned block
//   { texel(x): 16 ch, texel(min(x+1,63)): 16 ch }
// halfs per scale: 3*H*64*32 = 6144*H -> s0 786432, s1 1572864, s2 3145728, s3 6291456
// offsets: 786432 * (2^s - 1)
__device__ __align__(16) __half g_dup[11796480];

// -------- transpose+convert+duplicate: [3,16,H,64] fp32 -> 64B blocks --------
__global__ void __launch_bounds__(256) transpose_all(const float* __restrict__ g0,
                                                     const float* __restrict__ g1,
                                                     const float* __restrict__ g2,
                                                     const float* __restrict__ g3) {
    int idx = blockIdx.x * blockDim.x + threadIdx.x;
    if (idx >= 368640) return;   // 3*64*(128+256+512+1024)
    const float* g;
    int H, toff, local, hshift;
    if (idx < 24576)       { g = g0; H = 128;  toff = 0;       local = idx;          hshift = 7;  }
    else if (idx < 73728)  { g = g1; H = 256;  toff = 786432;  local = idx - 24576;  hshift = 8;  }
    else if (idx < 172032) { g = g2; H = 512;  toff = 2359296; local = idx - 73728;  hshift = 9;  }
    else                   { g = g3; H = 1024; toff = 5505024; local = idx - 172032; hshift = 10; }

    int w = local & 63;
    int rest = local >> 6;            // ci*H + h
    int h = rest & (H - 1);
    int ci = rest >> hshift;
    const float* src = g + ((size_t)(ci * 16) * H + h) * WRES + w;
    int dx = (w < 63) ? 1 : 0;        // clamp x+1 at edge
    size_t fstride = (size_t)H * WRES;

    float t0[16], t1[16];
#pragma unroll
    for (int f = 0; f < 16; f++) {
        t0[f] = src[f * fstride];
        t1[f] = src[f * fstride + dx];
    }

    __half2 hv[16];
#pragma unroll
    for (int f = 0; f < 8; f++) {
        hv[f]     = __floats2half2_rn(t0[2 * f], t0[2 * f + 1]);
        hv[8 + f] = __floats2half2_rn(t1[2 * f], t1[2 * f + 1]);
    }

    uint4* dst = reinterpret_cast<uint4*>(g_dup + toff + (size_t)local * 32);
    const uint32_t* u = reinterpret_cast<const uint32_t*>(hv);
#pragma unroll
    for (int q = 0; q < 4; q++)
        dst[q] = make_uint4(u[4 * q], u[4 * q + 1], u[4 * q + 2], u[4 * q + 3]);
}

// -------- main sample kernel: 4 lanes x 4 samples (all scales) per thread --------
// Group G = n*3 + ci handles j = ci, ci+3, ci+6, ci+9 (scales 0..3), sharing
// the x coordinate (pts[n,ci]) and the y source (radius[n]).
// lane r: bit0 = feature half, bit1 = x-corner -> in-block offset r*16B.
// Each group's row-load covers one 64B-aligned region -> exactly 1 line.
__global__ void __launch_bounds__(256) sample_k(const float* __restrict__ pts,
                                                const float* __restrict__ radius,
                                                float* __restrict__ out) {
    int t = blockIdx.x * blockDim.x + threadIdx.x;
    int G = t >> 2;               // 3M groups
    int r = t & 3;
    int n = G / 3;
    int ci = G - n * 3;           // 0..2

    float xv = __ldg(pts + n * 3 + ci);
    float yv = __ldg(radius + n);

    // shared x setup
    float fx = (xv + 1.0f) * 31.5f;
    float x0f = floorf(fx);
    float wx = fx - x0f;
    int x0 = min(max((int)x0f, 0), 63);
    float wxr = (r & 2) ? wx : (1.0f - wx);
    int lsel = r * 8;             // lane's 16B within the 64B block (halfs)
    float yp1 = yv + 1.0f;

    // per-scale y setup + 8 independent loads (MLP=8)
    uint4 v0[4], v1[4];
    float w0[4], w1[4];
#pragma unroll
    for (int s = 0; s < 4; s++) {
        int H = 128 << s;
        float fy = yp1 * (0.5f * (float)(H - 1));
        float y0f = floorf(fy);
        float wy = fy - y0f;
        int y0 = min(max((int)y0f, 0), H - 1);
        int y1i = min(y0 + 1, H - 1);
        int toff = 786432 * ((1 << s) - 1);
        const __half* tb = g_dup + toff + (size_t)(ci * H) * 2048;  // 2048 halfs/row
        v0[s] = *reinterpret_cast<const uint4*>(tb + ((size_t)(y0 << 6) + x0) * 32 + lsel);
        v1[s] = *reinterpret_cast<const uint4*>(tb + ((size_t)(y1i << 6) + x0) * 32 + lsel);
        w0[s] = (1.0f - wy) * wxr;
        w1[s] = wy * wxr;
    }

    // out base for this (n, ci, chunk): sample s lands at obase + s*48
    int chunk = ((r & 1) << 1) | (r >> 1);
    float* obase = out + (size_t)n * 192 + ci * 16 + chunk * 4;

#pragma unroll
    for (int s = 0; s < 4; s++) {
        const __half2* hA = reinterpret_cast<const __half2*>(&v0[s]);
        const __half2* hB = reinterpret_cast<const __half2*>(&v1[s]);
        float acc[8];
#pragma unroll
        for (int k = 0; k < 4; k++) {
            float2 a = __half22float2(hA[k]);
            float2 b = __half22float2(hB[k]);
            acc[2 * k]     = a.x * w0[s] + b.x * w1[s];
            acc[2 * k + 1] = a.y * w0[s] + b.y * w1[s];
        }
#pragma unroll
        for (int i = 0; i < 8; i++) acc[i] += __shfl_xor_sync(0xffffffffu, acc[i], 2);

        float4 st = (r & 2) ? make_float4(acc[4], acc[5], acc[6], acc[7])
                            : make_float4(acc[0], acc[1], acc[2], acc[3]);
        *reinterpret_cast<float4*>(obase + s * 48) = st;
    }
}

extern "C" void kernel_launch(void* const* d_in, const int* in_sizes, int n_in,
                              void* d_out, int out_size) {
    const float* pts    = (const float*)d_in[0];
    const float* radius = (const float*)d_in[1];
    float* out = (float*)d_out;

    transpose_all<<<(368640 + 255) / 256, 256>>>((const float*)d_in[2],
                                                 (const float*)d_in[3],
                                                 (const float*)d_in[4],
                                                 (const float*)d_in[5]);

    // 3M groups * 4 lanes = 12M threads; 256/block -> 46875 blocks exactly
    sample_k<<<46875, 256>>>(pts, radius, out);
}